// round 8
// baseline (speedup 1.0000x reference)
#include <cuda_runtime.h>
#include <cuda_bf16.h>
#include <cstdint>

// out[i, s] = sigmoid( sqrt(sum_j X[i,j]^2 * exp(lv[j])) * z[s] + sum_j X[i,j]*mu[j] )
// N = 500000 rows, D = 64, NS = 128.
//
// R6: cp.async-tiled pipeline.
//   - CTA stages 64-row tiles of X (16KB) to smem via cp.async.cg (no reg cost)
//   - double-buffered, 8 tiles/CTA: tile t+2 always in flight during compute(t)
//   - compute core = R5: half-warp per row, LDS.128 (conflict-free), butterfly
//     over 16 lanes, sigmoid via MUFU.TANH, STG.128 __stcs stores
//   - 32KB smem/CTA -> 6 CTA/SM (48 warps); grid = ceil(N/512) = 977 (~1 wave)

#define TILE_ROWS     64
#define TILE_BYTES    (TILE_ROWS * 256)            // 16384
#define TILES_PER_CTA 8
#define ROWS_PER_CTA  (TILE_ROWS * TILES_PER_CTA)  // 512

__device__ __forceinline__ void cp_async16(uint32_t dst, const char* src) {
    asm volatile("cp.async.cg.shared.global [%0], [%1], 16;" :: "r"(dst), "l"(src));
}
__device__ __forceinline__ void cp_commit() {
    asm volatile("cp.async.commit_group;");
}
template <int N>
__device__ __forceinline__ void cp_wait() {
    asm volatile("cp.async.wait_group %0;" :: "n"(N));
}

__device__ __forceinline__ float fast_tanh(float a) {
    float t;
    asm("tanh.approx.f32 %0, %1;" : "=f"(t) : "f"(a));
    return t;
}
__device__ __forceinline__ float fast_sqrt(float v) {
    float s;
    asm("sqrt.approx.f32 %0, %1;" : "=f"(s) : "f"(v));
    return s;
}

__device__ __forceinline__ void dot_pair(const float4& x, const float4& mu,
                                         const float4& ew, float& m, float& v) {
    m = x.x * mu.x;
    m = fmaf(x.y, mu.y, m);
    m = fmaf(x.z, mu.z, m);
    m = fmaf(x.w, mu.w, m);
    v = (x.x * x.x) * ew.x;
    v = fmaf(x.y * x.y, ew.y, v);
    v = fmaf(x.z * x.z, ew.z, v);
    v = fmaf(x.w * x.w, ew.w, v);
}

// zA/zB pre-scaled by 0.5; a/2 = sqrt(v)*(0.5 z) + 0.5 m
__device__ __forceinline__ void emit_row(float m, float v,
                                         const float4& zA, const float4& zB,
                                         float* __restrict__ orow, int hl) {
    const float s  = fast_sqrt(v);
    const float mh = 0.5f * m;
    float4 ra, rb;
    ra.x = fmaf(fast_tanh(fmaf(s, zA.x, mh)), 0.5f, 0.5f);
    ra.y = fmaf(fast_tanh(fmaf(s, zA.y, mh)), 0.5f, 0.5f);
    ra.z = fmaf(fast_tanh(fmaf(s, zA.z, mh)), 0.5f, 0.5f);
    ra.w = fmaf(fast_tanh(fmaf(s, zA.w, mh)), 0.5f, 0.5f);
    rb.x = fmaf(fast_tanh(fmaf(s, zB.x, mh)), 0.5f, 0.5f);
    rb.y = fmaf(fast_tanh(fmaf(s, zB.y, mh)), 0.5f, 0.5f);
    rb.z = fmaf(fast_tanh(fmaf(s, zB.z, mh)), 0.5f, 0.5f);
    rb.w = fmaf(fast_tanh(fmaf(s, zB.w, mh)), 0.5f, 0.5f);
    __stcs(reinterpret_cast<float4*>(orow) + hl, ra);
    __stcs(reinterpret_cast<float4*>(orow) + hl + 16, rb);
}

__global__ __launch_bounds__(256, 6) void blr_sigmoid_kernel(
    const float* __restrict__ X,
    const float* __restrict__ w_mu,
    const float* __restrict__ w_lv,
    const float* __restrict__ z,
    float* __restrict__ out,
    int n)
{
    __shared__ __align__(16) char smx[2][TILE_BYTES];

    const int tid  = threadIdx.x;
    const int lane = tid & 31;
    const int wid  = tid >> 5;          // 0..7
    const int hl   = lane & 15;
    const int half = lane >> 4;

    const int cta_row0 = blockIdx.x * ROWS_PER_CTA;
    const char* Xb = reinterpret_cast<const char*>(X);
    const uint32_t sm0 = (uint32_t)__cvta_generic_to_shared(smx[0]);
    const uint32_t sm1 = (uint32_t)__cvta_generic_to_shared(smx[1]);

    // ---- stage first two tiles (issued before constant setup for overlap) ----
    {
        // tile 0
        int row0 = cta_row0;
        int bytes_valid = (n - row0 < TILE_ROWS ? (n - row0) : TILE_ROWS) * 256;
        #pragma unroll
        for (int i = 0; i < 4; ++i) {
            int off = tid * 16 + i * 4096;
            if (off < bytes_valid)
                cp_async16(sm0 + off, Xb + (size_t)row0 * 256 + off);
        }
        cp_commit();
        // tile 1
        row0 = cta_row0 + TILE_ROWS;
        bytes_valid = (n - row0 < TILE_ROWS ? (n - row0) : TILE_ROWS) * 256;
        #pragma unroll
        for (int i = 0; i < 4; ++i) {
            int off = tid * 16 + i * 4096;
            if (off < bytes_valid)
                cp_async16(sm1 + off, Xb + (size_t)row0 * 256 + off);
        }
        cp_commit();
    }

    // ---- per-lane constants (overlaps cp.async latency) ----
    const float4 mu4 = reinterpret_cast<const float4*>(w_mu)[hl];
    const float4 lv4 = reinterpret_cast<const float4*>(w_lv)[hl];
    const float4 ew4 = make_float4(__expf(lv4.x), __expf(lv4.y),
                                   __expf(lv4.z), __expf(lv4.w));
    float4 zA = reinterpret_cast<const float4*>(z)[hl];
    float4 zB = reinterpret_cast<const float4*>(z)[hl + 16];
    zA.x *= 0.5f; zA.y *= 0.5f; zA.z *= 0.5f; zA.w *= 0.5f;
    zB.x *= 0.5f; zB.y *= 0.5f; zB.z *= 0.5f; zB.w *= 0.5f;

    // ---- main pipeline ----
    #pragma unroll 1
    for (int t = 0; t < TILES_PER_CTA; ++t) {
        const int buf = t & 1;
        const float4* smf = reinterpret_cast<const float4*>(smx[buf]);
        const int tile_g0 = cta_row0 + t * TILE_ROWS;

        cp_wait<1>();          // tile t landed (this thread's chunks)
        __syncthreads();       // all threads' chunks visible

        // warp handles local rows [wid*8, wid*8+8): two quads
        #pragma unroll
        for (int sub = 0; sub < 2; ++sub) {
            const int lq = wid * 8 + sub * 4;     // local quad base
            const int gq = tile_g0 + lq;          // global quad base
            if (gq < n) {                          // n%4==0 -> whole quad valid
                const int lr0 = lq + half;
                const int lr1 = lq + 2 + half;
                const float4 x0 = smf[lr0 * 16 + hl];
                const float4 x1 = smf[lr1 * 16 + hl];

                float m0, v0, m1, v1;
                dot_pair(x0, mu4, ew4, m0, v0);
                dot_pair(x1, mu4, ew4, m1, v1);

                #pragma unroll
                for (int o = 8; o > 0; o >>= 1) {
                    m0 += __shfl_xor_sync(0xffffffffu, m0, o);
                    v0 += __shfl_xor_sync(0xffffffffu, v0, o);
                    m1 += __shfl_xor_sync(0xffffffffu, m1, o);
                    v1 += __shfl_xor_sync(0xffffffffu, v1, o);
                }

                emit_row(m0, v0, zA, zB, out + (size_t)(gq + half) * 128, hl);
                emit_row(m1, v1, zA, zB, out + (size_t)(gq + 2 + half) * 128, hl);
            }
        }

        __syncthreads();       // everyone done reading buf before overwrite

        // prefetch tile t+2 into buf (empty/partial past the end; commit anyway
        // to keep the wait_group cadence aligned)
        {
            const int row0 = cta_row0 + (t + 2) * TILE_ROWS;
            const int rv = n - row0;
            const int bytes_valid = (rv <= 0 ? 0
                                   : (rv < TILE_ROWS ? rv : TILE_ROWS)) * 256;
            const uint32_t dst = buf ? sm1 : sm0;
            #pragma unroll
            for (int i = 0; i < 4; ++i) {
                int off = tid * 16 + i * 4096;
                if (off < bytes_valid)
                    cp_async16(dst + off, Xb + (size_t)row0 * 256 + off);
            }
            cp_commit();
        }
    }
}

extern "C" void kernel_launch(void* const* d_in, const int* in_sizes, int n_in,
                              void* d_out, int out_size) {
    const float* X    = (const float*)d_in[0];
    const float* w_mu = (const float*)d_in[1];
    const float* w_lv = (const float*)d_in[2];
    const float* z    = (const float*)d_in[3];
    float* out = (float*)d_out;

    const int n = in_sizes[0] / 64;   // 500000 rows
    const int blocks = (n + ROWS_PER_CTA - 1) / ROWS_PER_CTA;   // 977

    blr_sigmoid_kernel<<<blocks, 256>>>(X, w_mu, w_lv, z, out, n);
}

// round 9
// speedup vs baseline: 1.0999x; 1.0999x over previous
#include <cuda_runtime.h>
#include <cuda_bf16.h>
#include <cstdint>

// out[i, s] = sigmoid( sqrt(sum_j X[i,j]^2 * exp(lv[j])) * z[s] + sum_j X[i,j]*mu[j] )
// N = 500000 rows, D = 64, NS = 128.
//
// R9 = R5 (best: one-shot, half-warp/row, butterfly, MUFU.TANH, __ldcs/__stcs)
//      but 8 rows per warp: two quads, all four LDG.128 hoisted (MLP=4).
//      N % 8 == 0 so quads need no intra-quad guards.

__device__ __forceinline__ float fast_tanh(float a) {
    float t;
    asm("tanh.approx.f32 %0, %1;" : "=f"(t) : "f"(a));
    return t;
}
__device__ __forceinline__ float fast_sqrt(float v) {
    float s;
    asm("sqrt.approx.f32 %0, %1;" : "=f"(s) : "f"(v));
    return s;
}

__device__ __forceinline__ void dot_pair(const float4& x, const float4& mu,
                                         const float4& ew, float& m, float& v) {
    m = x.x * mu.x;
    m = fmaf(x.y, mu.y, m);
    m = fmaf(x.z, mu.z, m);
    m = fmaf(x.w, mu.w, m);
    v = (x.x * x.x) * ew.x;
    v = fmaf(x.y * x.y, ew.y, v);
    v = fmaf(x.z * x.z, ew.z, v);
    v = fmaf(x.w * x.w, ew.w, v);
}

// zA/zB pre-scaled by 0.5; a/2 = sqrt(v)*(0.5 z) + 0.5 m
__device__ __forceinline__ void emit_row(float m, float v,
                                         const float4& zA, const float4& zB,
                                         float* __restrict__ orow, int hl) {
    const float s  = fast_sqrt(v);
    const float mh = 0.5f * m;
    float4 ra, rb;
    ra.x = fmaf(fast_tanh(fmaf(s, zA.x, mh)), 0.5f, 0.5f);
    ra.y = fmaf(fast_tanh(fmaf(s, zA.y, mh)), 0.5f, 0.5f);
    ra.z = fmaf(fast_tanh(fmaf(s, zA.z, mh)), 0.5f, 0.5f);
    ra.w = fmaf(fast_tanh(fmaf(s, zA.w, mh)), 0.5f, 0.5f);
    rb.x = fmaf(fast_tanh(fmaf(s, zB.x, mh)), 0.5f, 0.5f);
    rb.y = fmaf(fast_tanh(fmaf(s, zB.y, mh)), 0.5f, 0.5f);
    rb.z = fmaf(fast_tanh(fmaf(s, zB.z, mh)), 0.5f, 0.5f);
    rb.w = fmaf(fast_tanh(fmaf(s, zB.w, mh)), 0.5f, 0.5f);
    __stcs(reinterpret_cast<float4*>(orow) + hl, ra);
    __stcs(reinterpret_cast<float4*>(orow) + hl + 16, rb);
}

__global__ __launch_bounds__(256) void blr_sigmoid_kernel(
    const float* __restrict__ X,
    const float* __restrict__ w_mu,
    const float* __restrict__ w_lv,
    const float* __restrict__ z,
    float* __restrict__ out,
    int n)
{
    const int lane = threadIdx.x & 31;
    const int hl   = lane & 15;          // position within half-warp
    const int half = lane >> 4;          // 0 or 1: which row of the pair
    const int warp_global = (blockIdx.x * blockDim.x + threadIdx.x) >> 5;

    // This warp owns rows [base, base+8). N % 8 == 0 -> fully valid or skip.
    const int base = warp_global * 8;
    if (base >= n) return;

    // All four row-loads hoisted: 4 back-to-back LDG.128 (MLP=4), streaming.
    const int r0 = base + half;          // quad 0
    const int r1 = base + 2 + half;
    const int r2 = base + 4 + half;      // quad 1
    const int r3 = base + 6 + half;
    const float4 x0 = __ldcs(reinterpret_cast<const float4*>(X + (size_t)r0 * 64) + hl);
    const float4 x1 = __ldcs(reinterpret_cast<const float4*>(X + (size_t)r1 * 64) + hl);
    const float4 x2 = __ldcs(reinterpret_cast<const float4*>(X + (size_t)r2 * 64) + hl);
    const float4 x3 = __ldcs(reinterpret_cast<const float4*>(X + (size_t)r3 * 64) + hl);

    // Per-lane constants (issued under the load shadow)
    const float4 mu4 = reinterpret_cast<const float4*>(w_mu)[hl];
    const float4 lv4 = reinterpret_cast<const float4*>(w_lv)[hl];
    const float4 ew4 = make_float4(__expf(lv4.x), __expf(lv4.y),
                                   __expf(lv4.z), __expf(lv4.w));
    float4 zA = reinterpret_cast<const float4*>(z)[hl];
    float4 zB = reinterpret_cast<const float4*>(z)[hl + 16];
    zA.x *= 0.5f; zA.y *= 0.5f; zA.z *= 0.5f; zA.w *= 0.5f;
    zB.x *= 0.5f; zB.y *= 0.5f; zB.z *= 0.5f; zB.w *= 0.5f;

    // ---- quad 0 ----
    float m0, v0, m1, v1;
    dot_pair(x0, mu4, ew4, m0, v0);
    dot_pair(x1, mu4, ew4, m1, v1);
    #pragma unroll
    for (int o = 8; o > 0; o >>= 1) {
        m0 += __shfl_xor_sync(0xffffffffu, m0, o);
        v0 += __shfl_xor_sync(0xffffffffu, v0, o);
        m1 += __shfl_xor_sync(0xffffffffu, m1, o);
        v1 += __shfl_xor_sync(0xffffffffu, v1, o);
    }
    emit_row(m0, v0, zA, zB, out + (size_t)r0 * 128, hl);
    emit_row(m1, v1, zA, zB, out + (size_t)r1 * 128, hl);

    // ---- quad 1 ----
    float m2, v2, m3, v3;
    dot_pair(x2, mu4, ew4, m2, v2);
    dot_pair(x3, mu4, ew4, m3, v3);
    #pragma unroll
    for (int o = 8; o > 0; o >>= 1) {
        m2 += __shfl_xor_sync(0xffffffffu, m2, o);
        v2 += __shfl_xor_sync(0xffffffffu, v2, o);
        m3 += __shfl_xor_sync(0xffffffffu, m3, o);
        v3 += __shfl_xor_sync(0xffffffffu, v3, o);
    }
    emit_row(m2, v2, zA, zB, out + (size_t)r2 * 128, hl);
    emit_row(m3, v3, zA, zB, out + (size_t)r3 * 128, hl);
}

extern "C" void kernel_launch(void* const* d_in, const int* in_sizes, int n_in,
                              void* d_out, int out_size) {
    const float* X    = (const float*)d_in[0];
    const float* w_mu = (const float*)d_in[1];
    const float* w_lv = (const float*)d_in[2];
    const float* z    = (const float*)d_in[3];
    float* out = (float*)d_out;

    const int n = in_sizes[0] / 64;                 // 500000 rows (n % 8 == 0)
    const int rows_per_block = 8 * (256 / 32);      // 8 rows/warp * 8 warps = 64
    const int blocks = (n + rows_per_block - 1) / rows_per_block;  // 7813

    blr_sigmoid_kernel<<<blocks, 256>>>(X, w_mu, w_lv, z, out, n);
}